// round 9
// baseline (speedup 1.0000x reference)
#include <cuda_runtime.h>
#include <cuda_bf16.h>
#include <math.h>
#include <stdint.h>

// Problem constants
#define BB 32
#define LL 4096
#define HH 256
#define NN 512
#define MROWS (BB * NN)       // 16384
#define KP 544                 // padded K for trip GEMM (515->544), 17 k32 tiles
#define KV 515
#define KG 512                 // K for gat GEMM, 32 k16 tiles
#define CSR 136
#define ECAP 128

// Scratch (device globals; no allocations allowed)
__device__ float g_cs[(size_t)BB * CSR * HH];
__device__ float g_node[(size_t)MROWS * HH];
__device__ float g_agg[(size_t)MROWS * 512];
__device__ __nv_bfloat16 g_wh[(size_t)HH * KP];    // W_trip^T hi [256][544]
__device__ __nv_bfloat16 g_wl[(size_t)HH * KP];    // W_trip^T lo
__device__ __nv_bfloat16 g_gwh[(size_t)HH * KG];   // W_gat^T hi [256][512]
__device__ __nv_bfloat16 g_gwl[(size_t)HH * KG];   // W_gat^T lo
__device__ float g_asrc[MROWS];
__device__ float g_ae[2];
__device__ int   g_hn[MROWS];
__device__ int   g_bedge[BB];
__device__ int   g_rowmap[MROWS];
__device__ int   g_cnt;

// ---------------------------------------------------------------------------
// helpers
// ---------------------------------------------------------------------------
__device__ __forceinline__ void cp16(uint32_t dst, const void* src) {
    asm volatile("cp.async.cg.shared.global [%0], [%1], 16;\n"
                 :: "r"(dst), "l"(src));
}
__device__ __forceinline__ void cp_commit() {
    asm volatile("cp.async.commit_group;\n");
}
__device__ __forceinline__ void cp_wait0() {
    asm volatile("cp.async.wait_group 0;\n");
}
__device__ __forceinline__ void split2(float a, float b, uint32_t& hi, uint32_t& lo) {
    __nv_bfloat16 ah = __float2bfloat16_rn(a);
    __nv_bfloat16 bh = __float2bfloat16_rn(b);
    __nv_bfloat16 al = __float2bfloat16_rn(a - __bfloat162float(ah));
    __nv_bfloat16 bl = __float2bfloat16_rn(b - __bfloat162float(bh));
    hi = ((uint32_t)__bfloat16_as_ushort(bh) << 16) | (uint32_t)__bfloat16_as_ushort(ah);
    lo = ((uint32_t)__bfloat16_as_ushort(bl) << 16) | (uint32_t)__bfloat16_as_ushort(bl ? bl : bl);
    lo = ((uint32_t)__bfloat16_as_ushort(bl) << 16) | (uint32_t)__bfloat16_as_ushort(al);
}
__device__ __forceinline__ void mma16816(float* d, const uint32_t* a, const uint32_t* b) {
    asm volatile(
        "mma.sync.aligned.m16n8k16.row.col.f32.bf16.bf16.f32 "
        "{%0,%1,%2,%3}, {%4,%5,%6,%7}, {%8,%9}, {%0,%1,%2,%3};"
        : "+f"(d[0]), "+f"(d[1]), "+f"(d[2]), "+f"(d[3])
        : "r"(a[0]), "r"(a[1]), "r"(a[2]), "r"(a[3]), "r"(b[0]), "r"(b[1]));
}
__device__ __forceinline__ void ldsm4(uint32_t* r, uint32_t addr) {
    asm volatile("ldmatrix.sync.aligned.m8n8.x4.shared.b16 {%0,%1,%2,%3}, [%4];"
        : "=r"(r[0]), "=r"(r[1]), "=r"(r[2]), "=r"(r[3]) : "r"(addr));
}
__device__ __forceinline__ uint32_t smem_u32(const void* p) {
    return (uint32_t)__cvta_generic_to_shared(p);
}

// ---------------------------------------------------------------------------
// K0: per-batch prefix sums over emb rows 0..134; zero g_asrc
// ---------------------------------------------------------------------------
__global__ void __launch_bounds__(HH) k_prefix(const float* __restrict__ emb)
{
    int b = blockIdx.x, h = threadIdx.x;
    const float* eb = emb + (size_t)b * LL * HH + h;
    float* cs = g_cs + ((size_t)b * CSR) * HH + h;
    float acc = 0.f;
    cs[0] = 0.f;
    #pragma unroll 5
    for (int r = 0; r < CSR - 1; r++) {
        acc += eb[(size_t)r * HH];
        cs[(size_t)(r + 1) * HH] = acc;
    }
    g_asrc[(b << 9) + h]       = 0.f;
    g_asrc[(b << 9) + 256 + h] = 0.f;
}

// ---------------------------------------------------------------------------
// K0b: a_e scalars + zero counters/flags
// ---------------------------------------------------------------------------
__global__ void __launch_bounds__(64) k_misc(
    const float* __restrict__ Wattn, const float* __restrict__ edge_emb)
{
    int wid = threadIdx.x >> 5, lane = threadIdx.x & 31;
    const float* er = edge_emb + wid * HH;
    float s = 0.f;
#pragma unroll
    for (int h = lane; h < HH; h += 32) {
        float x = er[h];
        x = x >= 0.f ? x : 0.2f * x;
        s += x * Wattn[2 * HH + h];
    }
#pragma unroll
    for (int o = 16; o; o >>= 1) s += __shfl_xor_sync(0xffffffffu, s, o);
    if (lane == 0) g_ae[wid] = s;
    if (threadIdx.x < BB) g_bedge[threadIdx.x] = 0;
    if (threadIdx.x == 63) g_cnt = 0;
}

// ---------------------------------------------------------------------------
// K0c: split+transpose W_trip -> g_wh/g_wl, W_gat -> g_gwh/g_gwl
// ---------------------------------------------------------------------------
__global__ void __launch_bounds__(256) k_prepw(
    const float* __restrict__ Wt, const float* __restrict__ Wg)
{
    int n = blockIdx.x;
    for (int k = threadIdx.x; k < KP; k += 256) {
        float v = (k < KV) ? Wt[(size_t)k * HH + n] : 0.f;
        __nv_bfloat16 h = __float2bfloat16_rn(v);
        __nv_bfloat16 l = __float2bfloat16_rn(v - __bfloat162float(h));
        g_wh[(size_t)n * KP + k] = h;
        g_wl[(size_t)n * KP + k] = l;
    }
    for (int k = threadIdx.x; k < KG; k += 256) {
        float v = Wg[(size_t)k * HH + n];
        __nv_bfloat16 h = __float2bfloat16_rn(v);
        __nv_bfloat16 l = __float2bfloat16_rn(v - __bfloat162float(h));
        g_gwh[(size_t)n * KG + k] = h;
        g_gwl[(size_t)n * KG + k] = l;
    }
}

// ---------------------------------------------------------------------------
// K1: trip GEMM, bf16 3-split MMA + ldmatrix, BK=32, dynamic smem.
// Block 64(M)x128(N), 8 warps (2m x 4n), warp tile 32x32.
// smem layout (bytes): sAh[2][64][40] @0 (10240), sAl @10240,
//                      sBh[2][128][40] @20480 (20480), sBl @40960. total 61440.
// ---------------------------------------------------------------------------
__global__ void __launch_bounds__(256) k_gemm_trip(
    const float* __restrict__ bias, const float* __restrict__ Wattn,
    const int* __restrict__ ast, const int* __restrict__ alen,
    const int* __restrict__ ost, const int* __restrict__ olen,
    const int* __restrict__ sid)
{
    extern __shared__ char dsm[];
    __nv_bfloat16* sAh = (__nv_bfloat16*)(dsm);
    __nv_bfloat16* sAl = (__nv_bfloat16*)(dsm + 10240);
    __nv_bfloat16* sBh = (__nv_bfloat16*)(dsm + 20480);
    __nv_bfloat16* sBl = (__nv_bfloat16*)(dsm + 40960);
    const int ASTE = 64 * 40;    // elems per A stage
    const int BSTE = 128 * 40;

    int bm = blockIdx.y * 64, bn = blockIdx.x * 128;
    int tid = threadIdx.x, wid = tid >> 5, lane = tid & 31;
    int wm = (wid >> 2) * 32, wn = (wid & 3) * 32;

    // A loader: thread -> (row, 8 k-values at l_c8)
    int l_row = tid >> 2;
    int l_c8 = (tid & 3) * 8;
    int grow = bm + l_row;
    int b = grow >> 9;
    int as = ast[grow], al = alen[grow], os = ost[grow], ol = olen[grow];
    int sd = sid[grow];
    const float* csb = g_cs + (size_t)b * CSR * HH;
    const float* a_hi = csb + (size_t)(as + al + 1) * HH;
    const float* a_lo = csb + (size_t)as * HH;
    const float* o_hi = csb + (size_t)(os + ol + 1) * HH;
    const float* o_lo = csb + (size_t)os * HH;
    float inva = 1.f / (float)(al + 1), invo = 1.f / (float)(ol + 1);

    // B loader: thread -> (row, 16 k-chunk)
    int b_row = tid >> 1, b_kh = (tid & 1) * 16;
    const __nv_bfloat16* wh_src = g_wh + (size_t)(bn + b_row) * KP + b_kh;
    const __nv_bfloat16* wl_src = g_wl + (size_t)(bn + b_row) * KP + b_kh;
    uint32_t bh_dst[2], bl_dst[2];
#pragma unroll
    for (int s = 0; s < 2; s++) {
        bh_dst[s] = smem_u32(sBh + s * BSTE + b_row * 40 + b_kh);
        bl_dst[s] = smem_u32(sBl + s * BSTE + b_row * 40 + b_kh);
    }
    uint32_t a_dst_h[2], a_dst_l[2];
#pragma unroll
    for (int s = 0; s < 2; s++) {
        a_dst_h[s] = 0;  // not used; direct pointer stores below
        a_dst_l[s] = 0;
    }
    (void)a_dst_h; (void)a_dst_l;

    // ldmatrix base byte-offsets (within a stage)
    uint32_t sAh0 = smem_u32(sAh), sAl0 = smem_u32(sAl);
    uint32_t sBh0 = smem_u32(sBh), sBl0 = smem_u32(sBl);
    uint32_t aoff = (wm + (lane & 15)) * 80 + ((lane >> 4) * 16);
    uint32_t boff = (wn + ((lane >> 4) * 8) + (lane & 7)) * 80 + (((lane >> 3) & 1) * 16);

    float acc[2][4][4];
#pragma unroll
    for (int mf = 0; mf < 2; mf++)
#pragma unroll
        for (int nf = 0; nf < 4; nf++)
#pragma unroll
            for (int r = 0; r < 4; r++) acc[mf][nf][r] = 0.f;

    const int NT = KP / 32;  // 17

    // prologue: stage 0 (c = l_c8 < 32 => region a)
    {
        float4 h0 = *(const float4*)(a_hi + l_c8);
        float4 h1 = *(const float4*)(a_hi + l_c8 + 4);
        float4 l0 = *(const float4*)(a_lo + l_c8);
        float4 l1 = *(const float4*)(a_lo + l_c8 + 4);
        uint32_t uh[4], ul[4];
        split2((h0.x - l0.x) * inva, (h0.y - l0.y) * inva, uh[0], ul[0]);
        split2((h0.z - l0.z) * inva, (h0.w - l0.w) * inva, uh[1], ul[1]);
        split2((h1.x - l1.x) * inva, (h1.y - l1.y) * inva, uh[2], ul[2]);
        split2((h1.z - l1.z) * inva, (h1.w - l1.w) * inva, uh[3], ul[3]);
        *(uint4*)(sAh + l_row * 40 + l_c8) = make_uint4(uh[0], uh[1], uh[2], uh[3]);
        *(uint4*)(sAl + l_row * 40 + l_c8) = make_uint4(ul[0], ul[1], ul[2], ul[3]);
        cp16(bh_dst[0], wh_src);      cp16(bh_dst[0] + 16, wh_src + 8);
        cp16(bl_dst[0], wl_src);      cp16(bl_dst[0] + 16, wl_src + 8);
        cp_commit(); cp_wait0();
        __syncthreads();
    }

    int cur = 0;
    for (int t = 0; t < NT; t++) {
        int nxt = cur ^ 1;
        bool hasnext = (t + 1 < NT);
        float4 h0, h1, l0, l1; int mode = 2; float inv = 0.f; int cc = 0;
        if (hasnext) {
            int kofs = (t + 1) * 32;
            const __nv_bfloat16* whp = wh_src + kofs;
            const __nv_bfloat16* wlp = wl_src + kofs;
            cp16(bh_dst[nxt], whp);      cp16(bh_dst[nxt] + 16, whp + 8);
            cp16(bl_dst[nxt], wlp);      cp16(bl_dst[nxt] + 16, wlp + 8);
            cp_commit();
            int c = kofs + l_c8;
            if (c < 256) {
                h0 = *(const float4*)(a_hi + c); h1 = *(const float4*)(a_hi + c + 4);
                l0 = *(const float4*)(a_lo + c); l1 = *(const float4*)(a_lo + c + 4);
                inv = inva; mode = 0;
            } else if (c < 512) {
                cc = c - 256;
                h0 = *(const float4*)(o_hi + cc); h1 = *(const float4*)(o_hi + cc + 4);
                l0 = *(const float4*)(o_lo + cc); l1 = *(const float4*)(o_lo + cc + 4);
                inv = invo; mode = 0;
            } else { mode = 1; cc = c - 512; }
        }

        // ---- ksub 0 ----
        {
            uint32_t Ah[2][4], Al[2][4], Bh[2][4], Bl[2][4];
            uint32_t ah = sAh0 + cur * (ASTE * 2) + aoff;
            uint32_t alb = sAl0 + cur * (ASTE * 2) + aoff;
            ldsm4(Ah[0], ah); ldsm4(Ah[1], ah + 16 * 80);
            ldsm4(Al[0], alb); ldsm4(Al[1], alb + 16 * 80);
            uint32_t bh = sBh0 + cur * (BSTE * 2) + boff;
            uint32_t blb = sBl0 + cur * (BSTE * 2) + boff;
            ldsm4(Bh[0], bh); ldsm4(Bh[1], bh + 16 * 80);
            ldsm4(Bl[0], blb); ldsm4(Bl[1], blb + 16 * 80);
#pragma unroll
            for (int mf = 0; mf < 2; mf++)
#pragma unroll
                for (int nf = 0; nf < 4; nf++)
                    mma16816(acc[mf][nf], Ah[mf], &Bh[nf >> 1][(nf & 1) * 2]);
#pragma unroll
            for (int mf = 0; mf < 2; mf++)
#pragma unroll
                for (int nf = 0; nf < 4; nf++)
                    mma16816(acc[mf][nf], Ah[mf], &Bl[nf >> 1][(nf & 1) * 2]);
#pragma unroll
            for (int mf = 0; mf < 2; mf++)
#pragma unroll
                for (int nf = 0; nf < 4; nf++)
                    mma16816(acc[mf][nf], Al[mf], &Bh[nf >> 1][(nf & 1) * 2]);
        }

        // convert & store next A (LDGs above have had the ksub0 phase to land)
        if (hasnext) {
            uint32_t uh[4], ul[4];
            if (mode == 0) {
                split2((h0.x - l0.x) * inv, (h0.y - l0.y) * inv, uh[0], ul[0]);
                split2((h0.z - l0.z) * inv, (h0.w - l0.w) * inv, uh[1], ul[1]);
                split2((h1.x - l1.x) * inv, (h1.y - l1.y) * inv, uh[2], ul[2]);
                split2((h1.z - l1.z) * inv, (h1.w - l1.w) * inv, uh[3], ul[3]);
            } else {
                float f[8];
#pragma unroll
                for (int i = 0; i < 8; i++) f[i] = (cc + i == sd) ? 1.f : 0.f;
                split2(f[0], f[1], uh[0], ul[0]);
                split2(f[2], f[3], uh[1], ul[1]);
                split2(f[4], f[5], uh[2], ul[2]);
                split2(f[6], f[7], uh[3], ul[3]);
            }
            *(uint4*)(sAh + nxt * ASTE + l_row * 40 + l_c8) = make_uint4(uh[0], uh[1], uh[2], uh[3]);
            *(uint4*)(sAl + nxt * ASTE + l_row * 40 + l_c8) = make_uint4(ul[0], ul[1], ul[2], ul[3]);
        }

        // ---- ksub 1 ----
        {
            uint32_t Ah[2][4], Al[2][4], Bh[2][4], Bl[2][4];
            uint32_t ah = sAh0 + cur * (ASTE * 2) + aoff + 32;
            uint32_t alb = sAl0 + cur * (ASTE * 2) + aoff + 32;
            ldsm4(Ah[0], ah); ldsm4(Ah[1], ah + 16 * 80);
            ldsm4(Al[0], alb); ldsm4(Al[1], alb + 16 * 80);
            uint32_t bh = sBh0 + cur * (BSTE * 2) + boff + 32;
            uint32_t blb = sBl0 + cur * (BSTE * 2) + boff + 32;
            ldsm4(Bh[0], bh); ldsm4(Bh[1], bh + 16 * 80);
            ldsm4(Bl[0], blb); ldsm4(Bl[1], blb + 16 * 80);
#pragma unroll
            for (int mf = 0; mf < 2; mf++)
#pragma unroll
                for (int nf = 0; nf < 4; nf++)
                    mma16816(acc[mf][nf], Ah[mf], &Bh[nf >> 1][(nf & 1) * 2]);
#pragma unroll
            for (int mf = 0; mf < 2; mf++)
#pragma unroll
                for (int nf = 0; nf < 4; nf++)
                    mma16816(acc[mf][nf], Ah[mf], &Bl[nf >> 1][(nf & 1) * 2]);
#pragma unroll
            for (int mf = 0; mf < 2; mf++)
#pragma unroll
                for (int nf = 0; nf < 4; nf++)
                    mma16816(acc[mf][nf], Al[mf], &Bh[nf >> 1][(nf & 1) * 2]);
        }

        if (hasnext) cp_wait0();
        __syncthreads();
        cur = nxt;
    }

    // NOTE: stage indexing — A stage stride is ASTE elems; above cur*(ASTE*2)
    // is in BYTES via u32 addresses (ASTE*2 bytes = 5120).  (consistent)

    // epilogue: bias + store + fused a_src partials
    int g = lane >> 2, tg = (lane & 3) * 2;
#pragma unroll
    for (int mf = 0; mf < 2; mf++) {
        int r0 = bm + wm + mf * 16 + g;
        float s0 = 0.f, s1 = 0.f;
#pragma unroll
        for (int nf = 0; nf < 4; nf++) {
            int col = bn + wn + nf * 8 + tg;
            float b0v = bias[col], b1v = bias[col + 1];
            float v00 = acc[mf][nf][0] + b0v, v01 = acc[mf][nf][1] + b1v;
            float v10 = acc[mf][nf][2] + b0v, v11 = acc[mf][nf][3] + b1v;
            *(float2*)(g_node + (size_t)r0 * HH + col)       = make_float2(v00, v01);
            *(float2*)(g_node + (size_t)(r0 + 8) * HH + col) = make_float2(v10, v11);
            float wa0 = Wattn[HH + col], wa1 = Wattn[HH + col + 1];
            float x;
            x = v00 >= 0.f ? v00 : 0.2f * v00; s0 += x * wa0;
            x = v01 >= 0.f ? v01 : 0.2f * v01; s0 += x * wa1;
            x = v10 >= 0.f ? v10 : 0.2f * v10; s1 += x * wa0;
            x = v11 >= 0.f ? v11 : 0.2f * v11; s1 += x * wa1;
        }
        s0 += __shfl_xor_sync(0xffffffffu, s0, 1);
        s0 += __shfl_xor_sync(0xffffffffu, s0, 2);
        s1 += __shfl_xor_sync(0xffffffffu, s1, 1);
        s1 += __shfl_xor_sync(0xffffffffu, s1, 2);
        if ((lane & 3) == 0) {
            atomicAdd(&g_asrc[r0], s0);
            atomicAdd(&g_asrc[r0 + 8], s1);
        }
    }
}

// ---------------------------------------------------------------------------
// K2: edges — warp per target, 8 targets per block (same batch).
// ---------------------------------------------------------------------------
__global__ void __launch_bounds__(256) k_edges(
    const int* __restrict__ ast, const int* __restrict__ alen,
    const int* __restrict__ ost, const int* __restrict__ olen,
    const float* __restrict__ edge_emb)
{
    int blk = blockIdx.x;
    int b = blk >> 6;
    int base = b << 9;
    int i0 = (blk & 63) << 3;
    int tid = threadIdx.x;
    int wid = tid >> 5, lane = tid & 31;
    int i = i0 + wid;
    int row = base + i;

    __shared__ int   sh_as[NN], sh_al[NN], sh_os[NN], sh_ol[NN];
    __shared__ int   s_ej[8][ECAP];
    __shared__ float s_ew[8][ECAP];

#pragma unroll
    for (int jj = tid; jj < NN; jj += 256) {
        sh_as[jj] = ast[base + jj]; sh_al[jj] = alen[base + jj];
        sh_os[jj] = ost[base + jj]; sh_ol[jj] = olen[base + jj];
    }
    __syncthreads();

    float ni[8];
#pragma unroll
    for (int q = 0; q < 8; q++) ni[q] = g_node[(size_t)row * HH + lane + 32 * q];

    int as_i = sh_as[i], al_i = sh_al[i], os_i = sh_os[i], ol_i = sh_ol[i];
    float ae0 = g_ae[0], ae1 = g_ae[1];
    int ne = 0;

    for (int c0 = 0; c0 < NN; c0 += 32) {
        int j = c0 + lane;
        bool fA = (j != i) && (sh_as[j] == as_i) && (sh_al[j] == al_i);
        bool fO = (j != i) && (sh_os[j] == os_i) && (sh_ol[j] == ol_i);
        unsigned bA = __ballot_sync(0xffffffffu, fA);
        unsigned bO = __ballot_sync(0xffffffffu, fO);
        unsigned m = bA | bO;
        while (m) {
            int bit = __ffs(m) - 1; m &= m - 1;
            int j2 = c0 + bit;
            const float* nj = g_node + (size_t)(base + j2) * HH;
            float d = 0.f;
#pragma unroll
            for (int q = 0; q < 8; q++) d += ni[q] * nj[lane + 32 * q];
#pragma unroll
            for (int o = 16; o; o >>= 1) d += __shfl_xor_sync(0xffffffffu, d, o);
            if (d > 0.f) {
                float sc = g_asrc[base + j2];
                if ((bA >> bit) & 1) {
                    if (ne < ECAP) {
                        if (lane == 0) { s_ej[wid][ne] = (j2 << 1); s_ew[wid][ne] = sc + ae0; }
                        ne++;
                    }
                }
                if ((bO >> bit) & 1) {
                    if (ne < ECAP) {
                        if (lane == 0) { s_ej[wid][ne] = (j2 << 1) | 1; s_ew[wid][ne] = sc + ae1; }
                        ne++;
                    }
                }
            }
        }
    }
    __syncwarp();

    if (ne == 0) {
        if (lane == 0) g_hn[row] = 0;
        return;
    }

    float mx = -1e30f;
    for (int e = lane; e < ne; e += 32) mx = fmaxf(mx, s_ew[wid][e]);
#pragma unroll
    for (int o = 16; o; o >>= 1) mx = fmaxf(mx, __shfl_xor_sync(0xffffffffu, mx, o));
    float s = 0.f;
    for (int e = lane; e < ne; e += 32) {
        float v = expf(s_ew[wid][e] - mx);
        s_ew[wid][e] = v; s += v;
    }
#pragma unroll
    for (int o = 16; o; o >>= 1) s += __shfl_xor_sync(0xffffffffu, s, o);
    float inv = 1.f / s;
    float a0 = 0.f, a1 = 0.f;
    for (int e = lane; e < ne; e += 32) {
        float v = s_ew[wid][e] * inv;
        s_ew[wid][e] = v;
        if (s_ej[wid][e] & 1) a1 += v; else a0 += v;
    }
#pragma unroll
    for (int o = 16; o; o >>= 1) {
        a0 += __shfl_xor_sync(0xffffffffu, a0, o);
        a1 += __shfl_xor_sync(0xffffffffu, a1, o);
    }
    __syncwarp();

    float an[8];
#pragma unroll
    for (int q = 0; q < 8; q++) an[q] = 0.f;
    for (int e = 0; e < ne; e++) {
        float w = s_ew[wid][e];
        const float* nj = g_node + (size_t)(base + (s_ej[wid][e] >> 1)) * HH;
#pragma unroll
        for (int q = 0; q < 8; q++) an[q] += w * nj[lane + 32 * q];
    }
    float* ag = g_agg + (size_t)row * 512;
#pragma unroll
    for (int q = 0; q < 8; q++) ag[lane + 32 * q] = an[q];
#pragma unroll
    for (int q = 0; q < 8; q++) {
        int h = lane + 32 * q;
        ag[HH + h] = a0 * edge_emb[h] + a1 * edge_emb[HH + h];
    }
    if (lane == 0) {
        g_hn[row] = 1;
        int pos = atomicAdd(&g_cnt, 1);
        g_rowmap[pos] = row;
        atomicOr(&g_bedge[b], 1);
    }
}

// ---------------------------------------------------------------------------
// K3: scatter node rows for hn==0 rows in edge-having batches
// ---------------------------------------------------------------------------
__global__ void __launch_bounds__(256) k_scatter_node(
    const int* __restrict__ ast, const int* __restrict__ ost,
    float* __restrict__ outp)
{
    int blk = blockIdx.x;
    int wid = threadIdx.x >> 5, lane = threadIdx.x & 31;
    int row = (blk << 3) + wid;
    int b = row >> 9;
    if (g_hn[row] || !g_bedge[b]) return;
    int c = (ast[row] + ost[row]) >> 1;
    const float* nr = g_node + (size_t)row * HH;
    float* o = outp + ((size_t)b * LL + c) * HH;
#pragma unroll
    for (int q = 0; q < 8; q++) {
        int h = lane + 32 * q;
        atomicAdd(o + h, nr[h]);
    }
}

// ---------------------------------------------------------------------------
// K4: compacted gat GEMM, bf16 3-split MMA + ldmatrix, BK=16 (static smem),
// term-outer MMA ordering.
// ---------------------------------------------------------------------------
__global__ void __launch_bounds__(256) k_gemm_gat(
    const float* __restrict__ bias,
    const int* __restrict__ ast, const int* __restrict__ ost,
    float* __restrict__ outp)
{
    int cnt = g_cnt;
    int bm = blockIdx.y * 64, bn = blockIdx.x * 128;
    if (bm >= cnt) return;

    __shared__ __nv_bfloat16 sAh[2][64][24], sAl[2][64][24];
    __shared__ __nv_bfloat16 sBh[2][128][24], sBl[2][128][24];

    int tid = threadIdx.x, wid = tid >> 5, lane = tid & 31;
    int wm = (wid >> 2) * 32, wn = (wid & 3) * 32;

    int l_row = tid >> 2;
    int l_c4 = (tid & 3) * 4;
    int ridx = bm + l_row;
    bool avalid = (ridx < cnt);
    const float* ap = avalid
        ? g_agg + (size_t)g_rowmap[ridx] * KG + l_c4 : g_agg;

    int b_row = tid >> 1, b_half = (tid & 1) * 8;
    const __nv_bfloat16* wh_src = g_gwh + (size_t)(bn + b_row) * KG + b_half;
    const __nv_bfloat16* wl_src = g_gwl + (size_t)(bn + b_row) * KG + b_half;
    uint32_t bh_dst[2], bl_dst[2];
#pragma unroll
    for (int s = 0; s < 2; s++) {
        bh_dst[s] = smem_u32(&sBh[s][b_row][b_half]);
        bl_dst[s] = smem_u32(&sBl[s][b_row][b_half]);
    }

    const int AST = 64 * 48, BST = 128 * 48;
    uint32_t ah0 = smem_u32(&sAh[0][0][0]) + (wm + (lane & 15)) * 48 + ((lane >> 4) * 16);
    uint32_t al0 = smem_u32(&sAl[0][0][0]) + (wm + (lane & 15)) * 48 + ((lane >> 4) * 16);
    int b_r = wn + ((lane >> 4) * 8) + (lane & 7);
    int b_cb = ((lane >> 3) & 1) * 16;
    uint32_t bh0 = smem_u32(&sBh[0][0][0]) + b_r * 48 + b_cb;
    uint32_t bl0 = smem_u32(&sBl[0][0][0]) + b_r * 48 + b_cb;

    float acc[2][4][4];
#pragma unroll
    for (int mf = 0; mf < 2; mf++)
#pragma unroll
        for (int nf = 0; nf < 4; nf++)
#pragma unroll
            for (int r = 0; r < 4; r++) acc[mf][nf][r] = 0.f;

    const int NT = KG / 16;  // 32

    {
        float4 f = make_float4(0.f, 0.f, 0.f, 0.f);
        if (avalid) f = *(const float4*)(ap);
        uint32_t h0, h1, l0, l1;
        split2(f.x, f.y, h0, l0);
        split2(f.z, f.w, h1, l1);
        *(uint2*)&sAh[0][l_row][l_c4] = make_uint2(h0, h1);
        *(uint2*)&sAl[0][l_row][l_c4] = make_uint2(l0, l1);
        cp16(bh_dst[0], wh_src);
        cp16(bl_dst[0], wl_src);
        cp_commit(); cp_wait0();
        __syncthreads();
    }

    int cur = 0;
    for (int t = 0; t < NT; t++) {
        int nxt = cur ^ 1;
        bool hasnext = (t + 1 < NT);
        float4 f = make_float4(0.f, 0.f, 0.f, 0.f);
        if (hasnext) {
            int kofs = (t + 1) * 16;
            cp16(bh_dst[nxt], wh_src + kofs);
            cp16(bl_dst[nxt], wl_src + kofs);
            cp_commit();
            if (avalid) f = *(const float4*)(ap + kofs);
        }

        uint32_t Ah[2][4], Al[2][4], Bh[2][4], Bl[2][4];
        uint32_t ah = ah0 + cur * AST, alb = al0 + cur * AST;
        ldsm4(Ah[0], ah); ldsm4(Ah[1], ah + 16 * 48);
        ldsm4(Al[0], alb); ldsm4(Al[1], alb + 16 * 48);
        uint32_t bh = bh0 + cur * BST, blb = bl0 + cur * BST;
        ldsm4(Bh[0], bh); ldsm4(Bh[1], bh + 16 * 48);
        ldsm4(Bl[0], blb); ldsm4(Bl[1], blb + 16 * 48);

#pragma unroll
        for (int mf = 0; mf < 2; mf++)
#pragma unroll
            for (int nf = 0; nf < 4; nf++)
                mma16816(acc[mf][nf], Ah[mf], &Bh[nf >> 1][(nf & 1) * 2]);
#pragma unroll
        for (int mf = 0; mf < 2; mf++)
#pragma unroll
            for (int nf = 0; nf < 4; nf++)
                mma16816(acc[mf][nf], Ah[mf], &Bl[nf >> 1][(nf & 1) * 2]);
#pragma unroll
        for (int mf = 0; mf < 2; mf++)
#pragma unroll
            for (int nf = 0; nf < 4; nf++)
                mma16816(acc[mf][nf], Al[mf], &Bh[nf >> 1][(nf & 1) * 2]);

        if (hasnext) {
            uint32_t h0, h1, l0, l1;
            split2(f.x, f.y, h0, l0);
            split2(f.z, f.w, h1, l1);
            *(uint2*)&sAh[nxt][l_row][l_c4] = make_uint2(h0, h1);
            *(uint2*)&sAl[nxt][l_row][l_c4] = make_uint2(l0, l1);
            cp_wait0();
        }
        __syncthreads();
        cur = nxt;
    }

    int g = lane >> 2, tg = (lane & 3) * 2;
#pragma unroll
    for (int mf = 0; mf < 2; mf++) {
        int idx0 = bm + wm + mf * 16 + g;
        int idx1 = idx0 + 8;
        float *o0 = 0, *o1 = 0;
        if (idx0 < cnt) {
            int row = g_rowmap[idx0];
            int c = (ast[row] + ost[row]) >> 1;
            o0 = outp + ((size_t)(row >> 9) * LL + c) * HH;
        }
        if (idx1 < cnt) {
            int row = g_rowmap[idx1];
            int c = (ast[row] + ost[row]) >> 1;
            o1 = outp + ((size_t)(row >> 9) * LL + c) * HH;
        }
#pragma unroll
        for (int nf = 0; nf < 4; nf++) {
            int col = bn + wn + nf * 8 + tg;
            float b0v = bias[col], b1v = bias[col + 1];
            if (o0) {
                atomicAdd(o0 + col,     fmaxf(acc[mf][nf][0] + b0v, 0.f));
                atomicAdd(o0 + col + 1, fmaxf(acc[mf][nf][1] + b1v, 0.f));
            }
            if (o1) {
                atomicAdd(o1 + col,     fmaxf(acc[mf][nf][2] + b0v, 0.f));
                atomicAdd(o1 + col + 1, fmaxf(acc[mf][nf][3] + b1v, 0.f));
            }
        }
    }
}

// ---------------------------------------------------------------------------
// launch
// ---------------------------------------------------------------------------
extern "C" void kernel_launch(void* const* d_in, const int* in_sizes, int n_in,
                              void* d_out, int out_size)
{
    const float* emb    = (const float*)d_in[0];
    const float* Wtrip  = (const float*)d_in[1];
    const float* btrip  = (const float*)d_in[2];
    const float* edgee  = (const float*)d_in[3];
    const float* Wattn  = (const float*)d_in[4];
    // d_in[5] = b_attn (constant over softmax axis -> cancels)
    const float* Wgat   = (const float*)d_in[6];
    const float* bgat   = (const float*)d_in[7];
    const int* ast  = (const int*)d_in[8];
    const int* alen = (const int*)d_in[9];
    const int* ost  = (const int*)d_in[10];
    const int* olen = (const int*)d_in[11];
    const int* sid  = (const int*)d_in[12];
    float* outp = (float*)d_out;

    static int s_attr_done = 0;
    if (!s_attr_done) {
        cudaFuncSetAttribute(k_gemm_trip,
                             cudaFuncAttributeMaxDynamicSharedMemorySize, 61440);
        s_attr_done = 1;
    }

    cudaMemcpyAsync(outp, emb, (size_t)BB * LL * HH * sizeof(float),
                    cudaMemcpyDeviceToDevice);

    k_prefix<<<BB, HH>>>(emb);
    k_misc<<<1, 64>>>(Wattn, edgee);
    k_prepw<<<HH, 256>>>(Wtrip, Wgat);
    {
        dim3 g(2, MROWS / 64);            // (2, 256)
        k_gemm_trip<<<g, 256, 61440>>>(btrip, Wattn, ast, alen, ost, olen, sid);
    }
    k_edges<<<MROWS / 8, 256>>>(ast, alen, ost, olen, edgee);
    k_scatter_node<<<MROWS / 8, 256>>>(ast, ost, outp);
    {
        dim3 g(2, MROWS / 64);            // (2, 256) — y tiles early-exit past g_cnt
        k_gemm_gat<<<g, 256>>>(bgat, ast, ost, outp);
    }
}